// round 14
// baseline (speedup 1.0000x reference)
#include <cuda_runtime.h>
#include <cuda_fp16.h>
#include <cstdint>

#define Nn 4096
#define DI 512
#define DO 128
#define NH 4
#define BM 128
#define BK 32
#define BSTR 36          // hgemm pair-permuted tile stride (floats)
#define WSTR 132         // hgemm W tile stride
#define HSTR 40          // fused tile row stride in halfs (80 B; ldmatrix conflict-free)
#define TILEH (BM * HSTR)  // 5120 halfs = 10 KB per tile

// ---------------- device scratch ----------------
__device__ __half g_hT[DO * Nn];   // h fp16, transposed [d][node] (B operand)
__device__ float g_p[NH * Nn], g_p2[NH * Nn];   // exp(el), exp(0.2 el)
__device__ float g_q[NH * Nn], g_q2[NH * Nn];   // exp(er), exp(0.2 er)

// ---------------- helpers ----------------
__device__ __forceinline__ uint32_t cvt_tf32(float x) {
    uint32_t r;
    asm("cvt.rna.tf32.f32 %0, %1;" : "=r"(r) : "f"(x));
    return r;
}
__device__ __forceinline__ void mma_tf32(float& c0, float& c1, float& c2, float& c3,
                                         uint32_t a0, uint32_t a1, uint32_t a2, uint32_t a3,
                                         uint32_t b0, uint32_t b1) {
    asm volatile("mma.sync.aligned.m16n8k8.row.col.f32.tf32.tf32.f32 "
                 "{%0,%1,%2,%3}, {%4,%5,%6,%7}, {%8,%9}, {%0,%1,%2,%3};"
                 : "+f"(c0), "+f"(c1), "+f"(c2), "+f"(c3)
                 : "r"(a0), "r"(a1), "r"(a2), "r"(a3), "r"(b0), "r"(b1));
}
__device__ __forceinline__ void mma_f16(float& c0, float& c1, float& c2, float& c3,
                                        uint32_t a0, uint32_t a1, uint32_t a2, uint32_t a3,
                                        uint32_t b0, uint32_t b1) {
    asm volatile("mma.sync.aligned.m16n8k16.row.col.f32.f16.f16.f32 "
                 "{%0,%1,%2,%3}, {%4,%5,%6,%7}, {%8,%9}, {%0,%1,%2,%3};"
                 : "+f"(c0), "+f"(c1), "+f"(c2), "+f"(c3)
                 : "r"(a0), "r"(a1), "r"(a2), "r"(a3), "r"(b0), "r"(b1));
}
__device__ __forceinline__ void lds64(uint32_t& x, uint32_t& y, const void* p) {
    asm volatile("ld.shared.v2.b32 {%0,%1}, [%2];" : "=r"(x), "=r"(y) : "l"(__cvta_generic_to_shared(p)));
}
__device__ __forceinline__ void sts32(void* p, uint32_t v) {
    asm volatile("st.shared.b32 [%0], %1;" :: "l"(__cvta_generic_to_shared(p)), "r"(v));
}
__device__ __forceinline__ void ldsm4(uint32_t& r0, uint32_t& r1, uint32_t& r2, uint32_t& r3,
                                      uint32_t addr) {
    asm volatile("ldmatrix.sync.aligned.m8n8.x4.shared.b16 {%0,%1,%2,%3}, [%4];"
                 : "=r"(r0), "=r"(r1), "=r"(r2), "=r"(r3) : "r"(addr));
}
#define CP_ASYNC16(dst_u32, src_ptr) \
    asm volatile("cp.async.ca.shared.global [%0], [%1], 16;" :: "r"(dst_u32), "l"(src_ptr))
#define CP_COMMIT()  asm volatile("cp.async.commit_group;" ::: "memory")
#define CP_WAIT0()   asm volatile("cp.async.wait_group 0;" ::: "memory")

// pair-permutation for fp32 tiles (hgemm): (j, j+4) adjacent
__device__ __forceinline__ int posk(int j) {
    return (j & 24) + ((j & 3) << 1) + ((j >> 2) & 1);
}

// ======================================================================
// Kernel 1: h = x @ W via mma.sync tf32, software-pipelined, node
// projections + factorized exps fused into epilogue (round-13, verbatim).
// ======================================================================
__global__ __launch_bounds__(256) void k_hgemm(const float* __restrict__ x,
                                               const float* __restrict__ W,
                                               const float* __restrict__ al,
                                               const float* __restrict__ ar) {
    __shared__ float xs[2][32 * BSTR];
    __shared__ float Ws[2][32 * WSTR];

    int t = threadIdx.x, lane = t & 31, warp = t >> 5;
    int g = lane >> 2, ctg = lane & 3;
    int i0 = blockIdx.x * 32;
    int wm = warp >> 2, wn = warp & 3;
    int rmA = wm * 16 + g;
    int n0 = wn * 32;

    float acc[4][4];
#pragma unroll
    for (int nt = 0; nt < 4; nt++)
#pragma unroll
        for (int c = 0; c < 4; c++) acc[nt][c] = 0.0f;

    int xrow = t >> 3, xkq = (t & 7) * 4;
    const float* xp = &x[(size_t)(i0 + xrow) * DI + xkq];

    float4 xv;
    float4 wv[4];

#define HG_LDG(K0)                                                              \
    do {                                                                        \
        xv = *reinterpret_cast<const float4*>(xp + (K0));                       \
        _Pragma("unroll")                                                       \
        for (int r = 0; r < 4; r++) {                                           \
            int f = t + 256 * r;                                                \
            int kr = f >> 5, nc = (f & 31) * 4;                                 \
            wv[r] = *reinterpret_cast<const float4*>(&W[(size_t)((K0) + kr) * DO + nc]); \
        }                                                                       \
    } while (0)

#define HG_STS(S)                                                               \
    do {                                                                        \
        float* dst = &xs[S][xrow * BSTR];                                       \
        dst[posk(xkq + 0)] = __uint_as_float(cvt_tf32(xv.x));                   \
        dst[posk(xkq + 1)] = __uint_as_float(cvt_tf32(xv.y));                   \
        dst[posk(xkq + 2)] = __uint_as_float(cvt_tf32(xv.z));                   \
        dst[posk(xkq + 3)] = __uint_as_float(cvt_tf32(xv.w));                   \
        _Pragma("unroll")                                                       \
        for (int r = 0; r < 4; r++) {                                           \
            int f = t + 256 * r;                                                \
            int kr = f >> 5, nc = (f & 31) * 4;                                 \
            float* wd = &Ws[S][kr * WSTR + nc];                                 \
            wd[0] = __uint_as_float(cvt_tf32(wv[r].x));                         \
            wd[1] = __uint_as_float(cvt_tf32(wv[r].y));                         \
            wd[2] = __uint_as_float(cvt_tf32(wv[r].z));                         \
            wd[3] = __uint_as_float(cvt_tf32(wv[r].w));                         \
        }                                                                       \
    } while (0)

    HG_LDG(0);
    HG_STS(0);
    HG_LDG(32);

    const int NST = DI / 32;   // 16
    for (int it = 0; it < NST; ++it) {
        __syncthreads();
        if (it + 1 < NST) {
            HG_STS((it + 1) & 1);
            int nk = (it + 2 < NST) ? (it + 2) * 32 : 0;
            HG_LDG(nk);
        }
        const float* xsb = xs[it & 1];
        const float* Wsb = Ws[it & 1];
#pragma unroll
        for (int kk = 0; kk < 4; kk++) {
            uint32_t a0, a2, a1, a3;
            lds64(a0, a2, &xsb[rmA * BSTR + kk * 8 + ctg * 2]);
            lds64(a1, a3, &xsb[(rmA + 8) * BSTR + kk * 8 + ctg * 2]);
#pragma unroll
            for (int nt = 0; nt < 4; nt++) {
                int n = n0 + nt * 8 + g;
                uint32_t b0 = __float_as_uint(Wsb[(kk * 8 + ctg) * WSTR + n]);
                uint32_t b1 = __float_as_uint(Wsb[(kk * 8 + ctg + 4) * WSTR + n]);
                mma_tf32(acc[nt][0], acc[nt][1], acc[nt][2], acc[nt][3],
                         a0, a1, a2, a3, b0, b1);
            }
        }
    }
#undef HG_LDG
#undef HG_STS

    // ---- epilogue A: write g_hT (fp16) + stage h rows into smem ----
    float* hrow_s = &Ws[0][0];
    int lrA = rmA, lrB = rmA + 8;
    int rA = i0 + lrA, rB = i0 + lrB;
#pragma unroll
    for (int nt = 0; nt < 4; nt++) {
        int col = n0 + nt * 8 + ctg * 2;
        hrow_s[lrA * 132 + col]     = acc[nt][0];
        hrow_s[lrA * 132 + col + 1] = acc[nt][1];
        hrow_s[lrB * 132 + col]     = acc[nt][2];
        hrow_s[lrB * 132 + col + 1] = acc[nt][3];
        g_hT[(size_t)col * Nn + rA]       = __float2half_rn(acc[nt][0]);
        g_hT[(size_t)(col + 1) * Nn + rA] = __float2half_rn(acc[nt][1]);
        g_hT[(size_t)col * Nn + rB]       = __float2half_rn(acc[nt][2]);
        g_hT[(size_t)(col + 1) * Nn + rB] = __float2half_rn(acc[nt][3]);
    }
    __syncthreads();

    // ---- epilogue B: per-node projections + exps ----
    float alv[NH][4], arv[NH][4];
#pragma unroll
    for (int hd = 0; hd < NH; hd++)
#pragma unroll
        for (int k = 0; k < 4; k++) {
            alv[hd][k] = al[hd * DO + lane + 32 * k];
            arv[hd][k] = ar[hd * DO + lane + 32 * k];
        }
#pragma unroll
    for (int r = 0; r < 4; r++) {
        int row = warp * 4 + r;
        int node = i0 + row;
        float h0 = hrow_s[row * 132 + lane];
        float h1 = hrow_s[row * 132 + lane + 32];
        float h2 = hrow_s[row * 132 + lane + 64];
        float h3 = hrow_s[row * 132 + lane + 96];
#pragma unroll
        for (int hd = 0; hd < NH; hd++) {
            float sl = h0 * alv[hd][0] + h1 * alv[hd][1] + h2 * alv[hd][2] + h3 * alv[hd][3];
            float sr = h0 * arv[hd][0] + h1 * arv[hd][1] + h2 * arv[hd][2] + h3 * arv[hd][3];
#pragma unroll
            for (int off = 16; off; off >>= 1) {
                sl += __shfl_xor_sync(0xffffffffu, sl, off);
                sr += __shfl_xor_sync(0xffffffffu, sr, off);
            }
            if (lane == 0) {
                int idx = hd * Nn + node;
                g_p[idx]  = expf(sl);
                g_p2[idx] = expf(0.2f * sl);
                g_q[idx]  = expf(sr);
                g_q2[idx] = expf(0.2f * sr);
            }
        }
    }
}

// ======================================================================
// Kernel 2: fused masked-attention GEMM. Round-13 algebra (fmax weights),
// canonical k-contiguous tiles (HSTR=40), ldmatrix.x4 fragment loads,
// cp.async h-tile staging.
// ======================================================================
__global__ __launch_bounds__(512, 1) void k_fused(const float* __restrict__ adj,
                                                  const float* __restrict__ bias,
                                                  float* __restrict__ out) {
    extern __shared__ __half dsm[];    // [w0][w1][h0][h1], each TILEH halfs
    __shared__ float rowsum_s[BM];

    int t = threadIdx.x, lane = t & 31, warp = t >> 5;
    int g = lane >> 2, ctg = lane & 3;
    int head = blockIdx.x;
    int i0   = blockIdx.y * BM;
    int rm   = (warp >> 2) * 32;
    int n0   = (warp & 3) * 32;

    uint32_t smem_u32 = (uint32_t)__cvta_generic_to_shared(dsm);

    // ---- producer role: 4 i-rows x j-pair ----
    int ph = lane >> 4;            // 0/1
    int pp = lane & 15;            // j-pair: j = 2pp, 2pp+1
    int prow[4];                   // rows 8*warp + 4*ph + {0..3} (bank-disjoint STS)
#pragma unroll
    for (int i = 0; i < 4; i++) prow[i] = 8 * warp + 4 * ph + i;

    float pi[4], p2i[4], rsum[4];
#pragma unroll
    for (int i = 0; i < 4; i++) {
        int idx = head * Nn + i0 + prow[i];
        pi[i] = g_p[idx]; p2i[i] = g_p2[idx];
        rsum[i] = 0.0f;
    }
    const float* adj_p0 = adj + (size_t)(i0 + prow[0]) * Nn + 2 * pp;
    const float* adj_p1 = adj + (size_t)(i0 + prow[1]) * Nn + 2 * pp;
    const float* adj_p2 = adj + (size_t)(i0 + prow[2]) * Nn + 2 * pp;
    const float* adj_p3 = adj + (size_t)(i0 + prow[3]) * Nn + 2 * pp;
    const float* q_b   = g_q  + head * Nn + 2 * pp;
    const float* q2_b  = g_q2 + head * Nn + 2 * pp;

    // h staging role: thread copies 16B (8 halfs) of row hn, chunk hc
    int hn = t >> 2, hc = t & 3;
    const __half* hT_base = g_hT + (size_t)hn * Nn + 8 * hc;
    uint32_t hdst_off = (uint32_t)(hn * HSTR + 8 * hc) * 2;   // bytes within h tile

    // ldmatrix per-lane byte offsets (within a tile)
    uint32_t offA0 = (uint32_t)(((rm + ((lane >> 3) & 1) * 8 + (lane & 7)) * HSTR
                                 + (lane >> 4) * 8) * 2);
    uint32_t offA1 = offA0 + 16 * HSTR * 2;
    uint32_t offB0 = (uint32_t)(((n0 + (lane >> 4) * 8 + (lane & 7)) * HSTR
                                 + ((lane >> 3) & 1) * 8) * 2);
    uint32_t offB1 = offB0 + 16 * HSTR * 2;

    float acc[2][4][4];
#pragma unroll
    for (int mt = 0; mt < 2; mt++)
#pragma unroll
        for (int nt = 0; nt < 4; nt++)
#pragma unroll
            for (int c = 0; c < 4; c++) acc[mt][nt][c] = 0.0f;

    float2 areg[4];
    float2 qj2, q2j2;

#define FU_LDG(K0)                                                            \
    do {                                                                      \
        areg[0] = *reinterpret_cast<const float2*>(adj_p0 + (K0));            \
        areg[1] = *reinterpret_cast<const float2*>(adj_p1 + (K0));            \
        areg[2] = *reinterpret_cast<const float2*>(adj_p2 + (K0));            \
        areg[3] = *reinterpret_cast<const float2*>(adj_p3 + (K0));            \
        qj2  = *reinterpret_cast<const float2*>(q_b + (K0));                  \
        q2j2 = *reinterpret_cast<const float2*>(q2_b + (K0));                 \
    } while (0)

#define FU_PROD(S, K0)                                                        \
    do {                                                                      \
        __half* ws = dsm + (S) * TILEH;                                       \
        _Pragma("unroll")                                                     \
        for (int i = 0; i < 4; i++) {                                         \
            float wa = areg[i].x * fmaxf(pi[i] * qj2.x, p2i[i] * q2j2.x);     \
            float wb = areg[i].y * fmaxf(pi[i] * qj2.y, p2i[i] * q2j2.y);     \
            __half2 wh2 = __floats2half2_rn(wa, wb);                          \
            rsum[i] += wa + wb;                                               \
            sts32(&ws[prow[i] * HSTR + 2 * pp],                               \
                  *reinterpret_cast<uint32_t*>(&wh2));                        \
        }                                                                     \
        uint32_t hdst = smem_u32 + (uint32_t)((2 + (S)) * TILEH * 2) + hdst_off; \
        CP_ASYNC16(hdst, hT_base + (K0));                                     \
        CP_COMMIT();                                                          \
    } while (0)

    // ---- prologue ----
    FU_LDG(0);
    FU_PROD(0, 0);
    FU_LDG(BK);

    const int NIT = Nn / BK;
    for (int it = 0; it < NIT; ++it) {
        CP_WAIT0();        // h(it) copies (issued last iteration) complete
        __syncthreads();   // all produce(it) + copies visible; mma(it-1) done

        if (it + 1 < NIT) {
            FU_PROD((it + 1) & 1, (it + 1) * BK);
            int nk0 = (it + 2 < NIT) ? (it + 2) * BK : 0;
            FU_LDG(nk0);
        }

        // ---- mma(it): ldmatrix.x4 fragments, 2 kk x 2 mt x 4 nt ----
        {
            uint32_t wsb = smem_u32 + (uint32_t)((it & 1) * TILEH * 2);
            uint32_t hsb = smem_u32 + (uint32_t)((2 + (it & 1)) * TILEH * 2);
#pragma unroll
            for (int kk = 0; kk < 2; kk++) {
                uint32_t kadd = kk * 32;   // 16 halfs
                uint32_t am0[4], am1[4], bA[4], bB[4];
                ldsm4(am0[0], am0[1], am0[2], am0[3], wsb + offA0 + kadd);
                ldsm4(am1[0], am1[1], am1[2], am1[3], wsb + offA1 + kadd);
                ldsm4(bA[0], bA[1], bA[2], bA[3], hsb + offB0 + kadd);  // nt0,nt1
                ldsm4(bB[0], bB[1], bB[2], bB[3], hsb + offB1 + kadd);  // nt2,nt3
#pragma unroll
                for (int mt = 0; mt < 2; mt++) {
                    uint32_t* am = mt ? am1 : am0;
                    mma_f16(acc[mt][0][0], acc[mt][0][1], acc[mt][0][2], acc[mt][0][3],
                            am[0], am[1], am[2], am[3], bA[0], bA[1]);
                    mma_f16(acc[mt][1][0], acc[mt][1][1], acc[mt][1][2], acc[mt][1][3],
                            am[0], am[1], am[2], am[3], bA[2], bA[3]);
                    mma_f16(acc[mt][2][0], acc[mt][2][1], acc[mt][2][2], acc[mt][2][3],
                            am[0], am[1], am[2], am[3], bB[0], bB[1]);
                    mma_f16(acc[mt][3][0], acc[mt][3][1], acc[mt][3][2], acc[mt][3][3],
                            am[0], am[1], am[2], am[3], bB[2], bB[3]);
                }
            }
        }
    }
#undef FU_LDG
#undef FU_PROD

    // ---- rowsum reduce within 16-lane groups ----
#pragma unroll
    for (int i = 0; i < 4; i++) {
        float v = rsum[i];
#pragma unroll
        for (int off = 8; off; off >>= 1) v += __shfl_xor_sync(0xffffffffu, v, off);
        if (pp == 0) rowsum_s[prow[i]] = v;
    }
    __syncthreads();

    // ---- epilogue: normalize + bias + store ----
#pragma unroll
    for (int mt = 0; mt < 2; mt++) {
        int lrA = rm + mt * 16 + g;
        int lrB = lrA + 8;
        float invA = 1.0f / fmaxf(rowsum_s[lrA], 1e-12f);
        float invB = 1.0f / fmaxf(rowsum_s[lrB], 1e-12f);
#pragma unroll
        for (int nt = 0; nt < 4; nt++) {
            int bcol = n0 + nt * 8 + ctg * 2;
            float2 bv = *reinterpret_cast<const float2*>(&bias[bcol]);
            float* opA = out + (size_t)(i0 + lrA) * (NH * DO) + head * DO + bcol;
            float* opB = out + (size_t)(i0 + lrB) * (NH * DO) + head * DO + bcol;
            *reinterpret_cast<float2*>(opA) =
                make_float2(acc[mt][nt][0] * invA + bv.x, acc[mt][nt][1] * invA + bv.y);
            *reinterpret_cast<float2*>(opB) =
                make_float2(acc[mt][nt][2] * invB + bv.x, acc[mt][nt][3] * invB + bv.y);
        }
    }
}

// ======================================================================
extern "C" void kernel_launch(void* const* d_in, const int* in_sizes, int n_in,
                              void* d_out, int out_size) {
    const float* adj = (const float*)d_in[0];
    const float* x   = (const float*)d_in[1];
    const float* W   = (const float*)d_in[2];
    const float* al  = (const float*)d_in[3];
    const float* ar  = (const float*)d_in[4];
    const float* b   = (const float*)d_in[5];
    float* out = (float*)d_out;

    const int dyn = 4 * TILEH * sizeof(__half);   // 40960 B
    cudaFuncSetAttribute(k_fused, cudaFuncAttributeMaxDynamicSharedMemorySize, dyn);

    k_hgemm<<<Nn / 32, 256>>>(x, W, al, ar);
    k_fused<<<dim3(NH, Nn / BM), 512, dyn>>>(adj, b, out);
}